// round 7
// baseline (speedup 1.0000x reference)
#include <cuda_runtime.h>
#include <cuda_bf16.h>
#include <cstdint>

#define DIM     1024
#define BATCH   16384
#define NLAYERS 18

// ---------------- GEMM tiling ----------------
#define BM 128
#define BN 128
#define BK 32                     // bf16 per K-chunk = 64B per row
#define NCHUNK (DIM / BK)         // 32

// smem stage: Ah/Al/Wh/Wl each 128 rows x 64B = 8KB -> stage 32KB, 3 stages = 96KB/CTA
#define OFF_AL 8192u
#define OFF_WH 16384u
#define OFF_WL 24576u
#define STAGE  32768u
#define SM_TOTAL (3 * 32768)

// ---------------- static device scratch ----------------
__device__ __align__(16) __nv_bfloat16 g_Wh[NLAYERS * DIM * DIM];
__device__ __align__(16) __nv_bfloat16 g_Wl[NLAYERS * DIM * DIM];
__device__ __align__(16) __nv_bfloat16 g_A0h[BATCH * DIM];
__device__ __align__(16) __nv_bfloat16 g_A0l[BATCH * DIM];
__device__ __align__(16) __nv_bfloat16 g_A1h[BATCH * DIM];
__device__ __align__(16) __nv_bfloat16 g_A1l[BATCH * DIM];
__device__ __align__(16) __nv_bfloat16 g_Rh [BATCH * DIM];
__device__ __align__(16) __nv_bfloat16 g_Rl [BATCH * DIM];

// ---------------- PTX helpers ----------------
__device__ __forceinline__ uint32_t smem_u32(const void* p) {
    uint32_t a;
    asm("{ .reg .u64 t; cvta.to.shared.u64 t, %1; cvt.u32.u64 %0, t; }" : "=r"(a) : "l"(p));
    return a;
}
#define CP_ASYNC16(dst, src) \
    asm volatile("cp.async.cg.shared.global [%0], [%1], 16;\n" :: "r"(dst), "l"(src))
#define CP_COMMIT() asm volatile("cp.async.commit_group;\n" ::: "memory")
#define CP_WAIT1()  asm volatile("cp.async.wait_group 1;\n" ::: "memory")
#define CP_WAIT0()  asm volatile("cp.async.wait_group 0;\n" ::: "memory")

#define LDSM_X4(r0, r1, r2, r3, addr) \
    asm volatile("ldmatrix.sync.aligned.m8n8.x4.shared.b16 {%0,%1,%2,%3}, [%4];\n" \
                 : "=r"(r0), "=r"(r1), "=r"(r2), "=r"(r3) : "r"(addr))

#define MMA4(d, a0, a1, a2, a3, b0, b1) \
    asm volatile("mma.sync.aligned.m16n8k16.row.col.f32.bf16.bf16.f32 " \
                 "{%0,%1,%2,%3},{%4,%5,%6,%7},{%8,%9},{%0,%1,%2,%3};\n" \
                 : "+f"((d)[0]), "+f"((d)[1]), "+f"((d)[2]), "+f"((d)[3]) \
                 : "r"(a0), "r"(a1), "r"(a2), "r"(a3), "r"(b0), "r"(b1))

__device__ __forceinline__ void split1(float v, __nv_bfloat16& h, __nv_bfloat16& l) {
    h = __float2bfloat16(v);
    l = __float2bfloat16(v - __bfloat162float(h));
}

// swizzle for 64B rows: 16B-group g XOR (row & 3) — conflict-free for both the
// cp.async stores and the ldmatrix 8-lane phases (verified passing in R6).
__device__ __forceinline__ uint32_t swz64(uint32_t row, uint32_t g16) {
    return row * 64u + ((g16 ^ (row & 3u)) << 4);
}

// stage loader: thread owns rows (tid>>2) and (tid>>2)+64, 16B group (tid&3),
// identical slots in each of the 4 arrays. d0 = swz64(tid>>2, tid&3).
// swz64(r+64,g) = swz64(r,g) + 4096.  off advances by 64 bytes per chunk.
__device__ __forceinline__ void load_chunk(
    uint32_t st, uint32_t d0,
    const char* a0, const char* a1, const char* a2, const char* a3, size_t off)
{
    CP_ASYNC16(st + d0,                   a0 + off);
    CP_ASYNC16(st + d0 + 4096u,           a0 + off + 131072);
    CP_ASYNC16(st + OFF_AL + d0,          a1 + off);
    CP_ASYNC16(st + OFF_AL + d0 + 4096u,  a1 + off + 131072);
    CP_ASYNC16(st + OFF_WH + d0,          a2 + off);
    CP_ASYNC16(st + OFF_WH + d0 + 4096u,  a2 + off + 131072);
    CP_ASYNC16(st + OFF_WL + d0,          a3 + off);
    CP_ASYNC16(st + OFF_WL + d0 + 4096u,  a3 + off + 131072);
    CP_COMMIT();
}

// ---------------- fused GEMM layer ----------------
// C[BM,BN] = A[BM,K] * W[BN,K]^T, 3-term bf16 split, fp32 accum.
// MODE 0: relu(C+bias)->bf16 pair | MODE 1: C+bias+res->bf16 pair | MODE 2: C+bias+res->fp32
template<int MODE>
__global__ void __launch_bounds__(256, 2)
k_gemm(const __nv_bfloat16* __restrict__ Ah, const __nv_bfloat16* __restrict__ Al,
       const __nv_bfloat16* __restrict__ Wh, const __nv_bfloat16* __restrict__ Wl,
       const float* __restrict__ bias,
       __nv_bfloat16* __restrict__ Oh, __nv_bfloat16* __restrict__ Ol,
       const __nv_bfloat16* __restrict__ Rh, const __nv_bfloat16* __restrict__ Rl,
       float* __restrict__ Of)
{
    extern __shared__ char smem[];
    const uint32_t sb = smem_u32(smem);
    const int tid = threadIdx.x, wid = tid >> 5, lane = tid & 31;
    const int Mb = blockIdx.y * BM, Nb = blockIdx.x * BN;
    const int wm = (wid & 1) * 64;          // 2 m-warps
    const int wn = (wid >> 1) * 32;         // 4 n-warps

    const char* pAh = (const char*)(Ah + (size_t)Mb * DIM);
    const char* pAl = (const char*)(Al + (size_t)Mb * DIM);
    const char* pWh = (const char*)(Wh + (size_t)Nb * DIM);
    const char* pWl = (const char*)(Wl + (size_t)Nb * DIM);

    // per-thread loader constants
    const uint32_t d0 = swz64((uint32_t)(tid >> 2), (uint32_t)(tid & 3));
    size_t goff = (size_t)(tid >> 2) * 2048 + (size_t)((tid & 3) * 16);

    // ldmatrix lane addressing
    const int l7  = lane & 7;
    const int l15 = lane & 15;
    const int lhi = lane >> 4;
    const int lb8 = ((lane >> 3) & 1) << 3;

    uint32_t adA[2][4], adB[2][2];
#pragma unroll
    for (int kk = 0; kk < 2; kk++) {
#pragma unroll
        for (int mi = 0; mi < 4; mi++) {
            uint32_t r = (uint32_t)(wm + mi * 16 + l15);
            adA[kk][mi] = swz64(r, (uint32_t)(2 * kk + lhi));
        }
#pragma unroll
        for (int j = 0; j < 2; j++) {
            uint32_t r = (uint32_t)(wn + j * 16 + l7 + lb8);
            adB[kk][j] = swz64(r, (uint32_t)(2 * kk + lhi));
        }
    }

    float acc[4][4][4];
#pragma unroll
    for (int mi = 0; mi < 4; mi++)
#pragma unroll
        for (int ni = 0; ni < 4; ni++)
#pragma unroll
            for (int k = 0; k < 4; k++) acc[mi][ni][k] = 0.f;

    // prologue: chunks 0 -> stage0, 1 -> stage1
    load_chunk(sb,         d0, pAh, pAl, pWh, pWl, goff);
    load_chunk(sb + STAGE, d0, pAh, pAl, pWh, pWl, goff + 64);

    uint32_t cs_off = 0, ls_off = 2 * STAGE;
    size_t gcur = goff + 128;

#pragma unroll 1
    for (int c = 0; c < NCHUNK; c++) {
        if (c < NCHUNK - 1) { CP_WAIT1(); } else { CP_WAIT0(); }
        __syncthreads();

        if (c + 2 < NCHUNK) {
            load_chunk(sb + ls_off, d0, pAh, pAl, pWh, pWl, gcur);
            gcur += 64;
            ls_off = (ls_off == 2 * STAGE) ? 0u : ls_off + STAGE;
        }

        const uint32_t st = sb + cs_off;
        cs_off = (cs_off == 2 * STAGE) ? 0u : cs_off + STAGE;
        const uint32_t stAh = st, stAl = st + OFF_AL, stWh = st + OFF_WH, stWl = st + OFF_WL;
#pragma unroll
        for (int kk = 0; kk < 2; kk++) {
            uint32_t aH[4][4], bH[2][4];
#pragma unroll
            for (int mi = 0; mi < 4; mi++)
                LDSM_X4(aH[mi][0], aH[mi][1], aH[mi][2], aH[mi][3], stAh + adA[kk][mi]);
#pragma unroll
            for (int j = 0; j < 2; j++)
                LDSM_X4(bH[j][0], bH[j][1], bH[j][2], bH[j][3], stWh + adB[kk][j]);
            // T1: Ah*Wh
#pragma unroll
            for (int mi = 0; mi < 4; mi++)
#pragma unroll
                for (int j = 0; j < 2; j++) {
                    MMA4(acc[mi][2 * j],     aH[mi][0], aH[mi][1], aH[mi][2], aH[mi][3], bH[j][0], bH[j][2]);
                    MMA4(acc[mi][2 * j + 1], aH[mi][0], aH[mi][1], aH[mi][2], aH[mi][3], bH[j][1], bH[j][3]);
                }
            // T3: Al*Wh (bH live)
            {
                uint32_t aL[4][4];
#pragma unroll
                for (int mi = 0; mi < 4; mi++)
                    LDSM_X4(aL[mi][0], aL[mi][1], aL[mi][2], aL[mi][3], stAl + adA[kk][mi]);
#pragma unroll
                for (int mi = 0; mi < 4; mi++)
#pragma unroll
                    for (int j = 0; j < 2; j++) {
                        MMA4(acc[mi][2 * j],     aL[mi][0], aL[mi][1], aL[mi][2], aL[mi][3], bH[j][0], bH[j][2]);
                        MMA4(acc[mi][2 * j + 1], aL[mi][0], aL[mi][1], aL[mi][2], aL[mi][3], bH[j][1], bH[j][3]);
                    }
            }
            // T2: Ah*Wl (aH live)
            {
                uint32_t bL[2][4];
#pragma unroll
                for (int j = 0; j < 2; j++)
                    LDSM_X4(bL[j][0], bL[j][1], bL[j][2], bL[j][3], stWl + adB[kk][j]);
#pragma unroll
                for (int mi = 0; mi < 4; mi++)
#pragma unroll
                    for (int j = 0; j < 2; j++) {
                        MMA4(acc[mi][2 * j],     aH[mi][0], aH[mi][1], aH[mi][2], aH[mi][3], bL[j][0], bL[j][2]);
                        MMA4(acc[mi][2 * j + 1], aH[mi][0], aH[mi][1], aH[mi][2], aH[mi][3], bL[j][1], bL[j][3]);
                    }
            }
        }
    }

    // ---- epilogue (verified fragment layout) ----
    auto emit = [&](int r, int c, float v0, float v1) {
        size_t off = (size_t)r * DIM + c;
        if (MODE >= 1) {
            __nv_bfloat162 rh2 = *reinterpret_cast<const __nv_bfloat162*>(Rh + off);
            __nv_bfloat162 rl2 = *reinterpret_cast<const __nv_bfloat162*>(Rl + off);
            v0 += __bfloat162float(rh2.x) + __bfloat162float(rl2.x);
            v1 += __bfloat162float(rh2.y) + __bfloat162float(rl2.y);
        }
        if (MODE == 0) { v0 = fmaxf(v0, 0.f); v1 = fmaxf(v1, 0.f); }
        if (MODE == 2) {
            *reinterpret_cast<float2*>(Of + off) = make_float2(v0, v1);
        } else {
            __nv_bfloat16 h0, l0, h1, l1;
            split1(v0, h0, l0); split1(v1, h1, l1);
            __nv_bfloat162 H; H.x = h0; H.y = h1;
            __nv_bfloat162 L; L.x = l0; L.y = l1;
            *reinterpret_cast<__nv_bfloat162*>(Oh + off) = H;
            *reinterpret_cast<__nv_bfloat162*>(Ol + off) = L;
        }
    };

    const int g  = lane >> 2;
    const int tg = lane & 3;
#pragma unroll
    for (int mi = 0; mi < 4; mi++) {
#pragma unroll
        for (int ni = 0; ni < 4; ni++) {
            int r0 = Mb + wm + mi * 16 + g;
            int c0 = Nb + wn + ni * 8 + tg * 2;
            float b0 = __ldg(bias + c0), b1 = __ldg(bias + c0 + 1);
            emit(r0,     c0, acc[mi][ni][0] + b0, acc[mi][ni][1] + b1);
            emit(r0 + 8, c0, acc[mi][ni][2] + b0, acc[mi][ni][3] + b1);
        }
    }
}

// ---------------- split input x ----------------
__global__ void k_split(const float* __restrict__ x,
                        __nv_bfloat16* __restrict__ oh, __nv_bfloat16* __restrict__ ol,
                        __nv_bfloat16* __restrict__ rh, __nv_bfloat16* __restrict__ rl) {
    int i4 = blockIdx.x * blockDim.x + threadIdx.x;
    float4 v = reinterpret_cast<const float4*>(x)[i4];
    __nv_bfloat16 h0,h1,h2,h3,l0,l1,l2,l3;
    split1(v.x,h0,l0); split1(v.y,h1,l1); split1(v.z,h2,l2); split1(v.w,h3,l3);
    __nv_bfloat162 H0; H0.x=h0; H0.y=h1;
    __nv_bfloat162 H1; H1.x=h2; H1.y=h3;
    __nv_bfloat162 L0; L0.x=l0; L0.y=l1;
    __nv_bfloat162 L1; L1.x=l2; L1.y=l3;
    __nv_bfloat162* OH = reinterpret_cast<__nv_bfloat162*>(oh);
    __nv_bfloat162* OL = reinterpret_cast<__nv_bfloat162*>(ol);
    __nv_bfloat162* RH = reinterpret_cast<__nv_bfloat162*>(rh);
    __nv_bfloat162* RL = reinterpret_cast<__nv_bfloat162*>(rl);
    int b = i4 * 2;
    OH[b] = H0; OH[b+1] = H1;
    OL[b] = L0; OL[b+1] = L1;
    RH[b] = H0; RH[b+1] = H1;
    RL[b] = L0; RL[b+1] = L1;
}

// ---------------- dequant + fold LoRA ----------------
__global__ void k_prep(const int* __restrict__ qw, const float* __restrict__ scale,
                       const float* __restrict__ la, const float* __restrict__ lb) {
    int idx = blockIdx.x * 256 + threadIdx.x;
    int l   = idx >> 20;
    int rem = idx & 0xFFFFF;
    int o   = rem >> 10;
    int i   = rem & 1023;
    float q = (float)qw[idx];
    float s = scale[(l << 16) + (o << 6) + (i >> 4)];
    float w = (q / 15.0f * 2.0f - 1.0f) * s;
    const float* lar = la + l * (32 * DIM) + i;
    const float* lbr = lb + l * (DIM * 32) + o * 32;
#pragma unroll
    for (int r = 0; r < 32; r++)
        w += lbr[r] * lar[r * DIM];
    __nv_bfloat16 wh, wl;
    split1(w, wh, wl);
    g_Wh[idx] = wh;
    g_Wl[idx] = wl;
}

// ---------------- LayerNorm ----------------
__device__ __forceinline__ float blockSum256(float v, float* red) {
#pragma unroll
    for (int o = 16; o > 0; o >>= 1) v += __shfl_xor_sync(0xffffffffu, v, o);
    int w = threadIdx.x >> 5;
    if ((threadIdx.x & 31) == 0) red[w] = v;
    __syncthreads();
    float t = 0.f;
#pragma unroll
    for (int i = 0; i < 8; i++) t += red[i];
    __syncthreads();
    return t;
}

__global__ void k_ln(const __nv_bfloat16* __restrict__ Ih, const __nv_bfloat16* __restrict__ Il,
                     const float* __restrict__ gw, const float* __restrict__ gb,
                     __nv_bfloat16* __restrict__ Oh, __nv_bfloat16* __restrict__ Ol,
                     __nv_bfloat16* __restrict__ R2h, __nv_bfloat16* __restrict__ R2l)
{
    __shared__ float red[8];
    const int row = blockIdx.x;
    const int tid = threadIdx.x;
    const size_t base = (size_t)row * DIM;
    float x[4];
#pragma unroll
    for (int j = 0; j < 4; j++) {
        int c = tid + j * 256;
        x[j] = __bfloat162float(Ih[base + c]) + __bfloat162float(Il[base + c]);
    }
    float s = x[0] + x[1] + x[2] + x[3];
    float mu = blockSum256(s, red) * (1.0f / DIM);
    float d[4], s2 = 0.f;
#pragma unroll
    for (int j = 0; j < 4; j++) { d[j] = x[j] - mu; s2 += d[j] * d[j]; }
    float var = blockSum256(s2, red) * (1.0f / DIM);
    float inv = rsqrtf(var + 1e-5f);
#pragma unroll
    for (int j = 0; j < 4; j++) {
        int c = tid + j * 256;
        float y = d[j] * inv * gw[c] + gb[c];
        __nv_bfloat16 h, l;
        split1(y, h, l);
        Oh[base + c] = h;  Ol[base + c] = l;
        R2h[base + c] = h; R2l[base + c] = l;
    }
}

// ---------------- orchestration ----------------
extern "C" void kernel_launch(void* const* d_in, const int* in_sizes, int n_in,
                              void* d_out, int out_size) {
    (void)in_sizes; (void)n_in; (void)out_size;
    const float* x     = (const float*)d_in[0];
    const float* scale = (const float*)d_in[1];
    const float* bias  = (const float*)d_in[2];
    const float* la    = (const float*)d_in[3];
    const float* lb    = (const float*)d_in[4];
    const float* lnw   = (const float*)d_in[5];
    const float* lnb   = (const float*)d_in[6];
    const int*   qw    = (const int*)d_in[7];

    __nv_bfloat16 *Wh, *Wl, *A0h, *A0l, *A1h, *A1l, *Rh, *Rl;
    cudaGetSymbolAddress((void**)&Wh,  g_Wh);
    cudaGetSymbolAddress((void**)&Wl,  g_Wl);
    cudaGetSymbolAddress((void**)&A0h, g_A0h);
    cudaGetSymbolAddress((void**)&A0l, g_A0l);
    cudaGetSymbolAddress((void**)&A1h, g_A1h);
    cudaGetSymbolAddress((void**)&A1l, g_A1l);
    cudaGetSymbolAddress((void**)&Rh,  g_Rh);
    cudaGetSymbolAddress((void**)&Rl,  g_Rl);

    cudaFuncSetAttribute(k_gemm<0>, cudaFuncAttributeMaxDynamicSharedMemorySize, SM_TOTAL);
    cudaFuncSetAttribute(k_gemm<1>, cudaFuncAttributeMaxDynamicSharedMemorySize, SM_TOTAL);
    cudaFuncSetAttribute(k_gemm<2>, cudaFuncAttributeMaxDynamicSharedMemorySize, SM_TOTAL);

    k_split<<<BATCH * DIM / 4 / 256, 256>>>(x, A0h, A0l, Rh, Rl);
    k_prep <<<NLAYERS * DIM * DIM / 256, 256>>>(qw, scale, la, lb);

    dim3 ggrid(DIM / BN, BATCH / BM);   // (8, 128)
    int li = 0;
    for (int blk = 0; blk < 6; ++blk) {
        const int W0 = li * DIM * DIM;
        k_gemm<0><<<ggrid, 256, SM_TOTAL>>>(A0h, A0l, Wh + W0, Wl + W0, bias + li * DIM,
                                            A1h, A1l, nullptr, nullptr, nullptr);
        li++;
        const int W1 = li * DIM * DIM;
        k_gemm<0><<<ggrid, 256, SM_TOTAL>>>(A1h, A1l, Wh + W1, Wl + W1, bias + li * DIM,
                                            A0h, A0l, nullptr, nullptr, nullptr);
        li++;
        const int W2 = li * DIM * DIM;
        if (blk < 5) {
            k_gemm<1><<<ggrid, 256, SM_TOTAL>>>(A0h, A0l, Wh + W2, Wl + W2, bias + li * DIM,
                                                A1h, A1l, Rh, Rl, nullptr);
            li++;
            k_ln<<<BATCH, 256>>>(A1h, A1l, lnw + blk * DIM, lnb + blk * DIM,
                                 A0h, A0l, Rh, Rl);
        } else {
            k_gemm<2><<<ggrid, 256, SM_TOTAL>>>(A0h, A0l, Wh + W2, Wl + W2, bias + li * DIM,
                                                nullptr, nullptr, Rh, Rl, (float*)d_out);
            li++;
        }
    }
}